// round 1
// baseline (speedup 1.0000x reference)
#include <cuda_runtime.h>
#include <cuda_bf16.h>
#include <math.h>

#define Bsz 8
#define Lseq 2048
#define Dd 128
#define NROWS (Bsz * Lseq)          // 16384
#define BLD (NROWS * Dd)            // 2097152
#define BDD (Bsz * Dd * Dd)         // 131072

// ---------------- scratch (device globals; no allocation) ----------------
__device__ float g_qkv[NROWS * 512];   // x @ W_in^T
__device__ float g_g  [NROWS * 256];   // sigmoid(gate @ W_gate^T)
__device__ float g_pk [NROWS * 640];   // packed per-(b,t): q,k,v,alpha,beta (128 each)
__device__ float g_res[NROWS * Dd];    // x @ W_res^T
__device__ float g_out[NROWS * Dd];    // scan outputs (silu(q@S))
__device__ float g_ol [NROWS * Dd];    // outs @ W_out^T

__device__ __forceinline__ float sigf(float x) { return 1.f / (1.f + __expf(-x)); }

// ---------------- generic GEMM: C[n,m] = sum_d A[n,d]*W[m,d] --------------
// N = 16384 rows (fixed), K = 128 (fixed), M multiple of 64.
template <bool SIG>
__global__ void __launch_bounds__(256) gemm_kernel(const float* __restrict__ A, int lda,
                                                   const float* __restrict__ W,
                                                   float* __restrict__ C, int ldc) {
    __shared__ float As[64][17];
    __shared__ float Ws[64][17];
    int bx = blockIdx.x;      // col tile
    int by = blockIdx.y;      // row tile
    int tid = threadIdx.x;
    int tx = tid & 15;
    int ty = tid >> 4;
    int lr  = tid >> 2;       // 0..63 load row
    int lk0 = (tid & 3) * 4;  // 0,4,8,12

    float acc[4][4];
#pragma unroll
    for (int m = 0; m < 4; m++)
#pragma unroll
        for (int n = 0; n < 4; n++) acc[m][n] = 0.f;

    const float* Arow = A + (size_t)(by * 64 + lr) * lda;
    const float* Wrow = W + (size_t)(bx * 64 + lr) * 128;

#pragma unroll 1
    for (int kt = 0; kt < 8; kt++) {
        int k0 = kt * 16;
        float4 av = *reinterpret_cast<const float4*>(Arow + k0 + lk0);
        float4 wv = *reinterpret_cast<const float4*>(Wrow + k0 + lk0);
        As[lr][lk0 + 0] = av.x; As[lr][lk0 + 1] = av.y;
        As[lr][lk0 + 2] = av.z; As[lr][lk0 + 3] = av.w;
        Ws[lr][lk0 + 0] = wv.x; Ws[lr][lk0 + 1] = wv.y;
        Ws[lr][lk0 + 2] = wv.z; Ws[lr][lk0 + 3] = wv.w;
        __syncthreads();
#pragma unroll
        for (int kk = 0; kk < 16; kk++) {
            float a[4], w[4];
#pragma unroll
            for (int m = 0; m < 4; m++) a[m] = As[ty + 16 * m][kk];
#pragma unroll
            for (int n = 0; n < 4; n++) w[n] = Ws[tx + 16 * n][kk];
#pragma unroll
            for (int m = 0; m < 4; m++)
#pragma unroll
                for (int n = 0; n < 4; n++) acc[m][n] = fmaf(a[m], w[n], acc[m][n]);
        }
        __syncthreads();
    }
#pragma unroll
    for (int m = 0; m < 4; m++) {
        int row = by * 64 + ty + 16 * m;
#pragma unroll
        for (int n = 0; n < 4; n++) {
            int col = bx * 64 + tx + 16 * n;
            float v = acc[m][n];
            if (SIG) v = sigf(v);
            C[(size_t)row * ldc + col] = v;
        }
    }
}

// ------------- depthwise conv(K=3) + sigmoid + L2 norm + pack -------------
__global__ void __launch_bounds__(128) convpack_kernel(const float* __restrict__ qw,
                                                       const float* __restrict__ qb,
                                                       const float* __restrict__ kw,
                                                       const float* __restrict__ kb) {
    int n = blockIdx.x;           // b*L + l
    int l = n & (Lseq - 1);
    int d = threadIdx.x;
    int lane = d & 31, w = d >> 5;
    __shared__ float redq[4], redk[4];

    const float* row = g_qkv + (size_t)n * 512;
    // q channel (cols 0..127)
    float qm = (l > 0)        ? row[-512 + d] : 0.f;
    float qc = row[d];
    float qp = (l < Lseq - 1) ? row[512 + d] : 0.f;
    float yq = fmaf(qw[d * 3 + 0], qm, fmaf(qw[d * 3 + 1], qc, fmaf(qw[d * 3 + 2], qp, qb[d])));
    float sq = sigf(yq);
    // k channel (cols 128..255)
    float km = (l > 0)        ? row[-512 + 128 + d] : 0.f;
    float kc = row[128 + d];
    float kp = (l < Lseq - 1) ? row[512 + 128 + d] : 0.f;
    float yk = fmaf(kw[d * 3 + 0], km, fmaf(kw[d * 3 + 1], kc, fmaf(kw[d * 3 + 2], kp, kb[d])));
    float sk = sigf(yk);

    float ssq = sq * sq, ssk = sk * sk;
#pragma unroll
    for (int o = 16; o >= 1; o >>= 1) {
        ssq += __shfl_xor_sync(0xffffffffu, ssq, o);
        ssk += __shfl_xor_sync(0xffffffffu, ssk, o);
    }
    if (lane == 0) { redq[w] = ssq; redk[w] = ssk; }
    __syncthreads();
    float nq = sqrtf(redq[0] + redq[1] + redq[2] + redq[3]);
    float nk = sqrtf(redk[0] + redk[1] + redk[2] + redk[3]);
    float qn = sq / fmaxf(nq, 1e-12f);
    float kn = sk / fmaxf(nk, 1e-12f);

    float* out = g_pk + (size_t)n * 640;
    out[d]       = qn;
    out[128 + d] = kn;
    out[256 + d] = row[256 + d];                       // v
    out[384 + d] = g_g[(size_t)n * 256 + d];           // alpha
    out[512 + d] = g_g[(size_t)n * 256 + 128 + d];     // beta
}

// ------------------------- sequential delta-rule scan ---------------------
// One CTA per batch. 512 threads: tid = ig*128 + jt. Thread owns S[i0..i0+32, jt].
__global__ void __launch_bounds__(512, 1) scan_kernel(const float* __restrict__ state,
                                                      float* __restrict__ sfin) {
    int b = blockIdx.x;
    int tid = threadIdx.x;
    int jt = tid & 127;
    int ig = tid >> 7;            // 0..3
    int lane = tid & 31;
    int warp = tid >> 5;          // 0..15
    int jtg = (tid >> 5) & 3;     // which 32-column group within the 128 columns
    int i0 = ig * 32;

    __shared__ float buf[2][640];
    __shared__ float u_part[4][128];
    __shared__ float sk_part[4][128];
    __shared__ float shSk[128];
    __shared__ float qvp[4], qskp[4];

    float S[32];
    const float* st = state + (size_t)b * Dd * Dd;
#pragma unroll
    for (int ii = 0; ii < 32; ii++) S[ii] = st[(size_t)(i0 + ii) * Dd + jt];

    const float* pkb = g_pk + (size_t)b * Lseq * 640;
    for (int idx = tid; idx < 640; idx += 512) buf[0][idx] = pkb[idx];
    __syncthreads();

    float* outb = g_out + (size_t)b * Lseq * Dd;

    for (int t = 0; t < Lseq; t++) {
        const float* cur = buf[t & 1];
        float kj  = cur[128 + jt];
        float aj  = cur[384 + jt];
        float bj  = cur[512 + jt];
        float bkj = bj * kj;
        float dj  = aj * bkj;

        // prefetch next step (distinct smem buffer)
        if (t + 1 < Lseq) {
            const float* nxt = pkb + (size_t)(t + 1) * 640;
            float* nb = buf[(t + 1) & 1];
            for (int idx = tid; idx < 640; idx += 512) nb[idx] = nxt[idx];
        }

        // phase 1: u partial (over my rows), Sk contributions
        float upart = 0.f;
        float a[32];
#pragma unroll
        for (int ii = 0; ii < 32; ii++) {
            float s = S[ii];
            upart = fmaf(cur[i0 + ii], s, upart);   // q · S_old column partial
            a[ii] = s * kj;
        }
        // warp transpose-reduce: after this, a[0] at lane l = sum over warp's 32 jt
        // of S[i0+l, jt]*k[jt]
#pragma unroll
        for (int o = 16; o >= 1; o >>= 1) {
            bool up = (lane & o) != 0;
#pragma unroll
            for (int m = 0; m < o; m++) {
                float keep = up ? a[m + o] : a[m];
                float give = up ? a[m] : a[m + o];
                float recv = __shfl_xor_sync(0xffffffffu, give, o);
                a[m] = keep + recv;
            }
        }
        u_part[ig][jt] = upart;
        sk_part[jtg][i0 + lane] = a[0];
        __syncthreads();

        // phase 2: combine Sk, scalar reductions q·v and q·Sk
        if (tid < 128) {
            int i = tid;
            float sk = sk_part[0][i] + sk_part[1][i] + sk_part[2][i] + sk_part[3][i];
            shSk[i] = sk;
            float qi = cur[i];
            float pv = qi * cur[256 + i];
            float ps = qi * sk;
#pragma unroll
            for (int o = 16; o >= 1; o >>= 1) {
                pv += __shfl_xor_sync(0xffffffffu, pv, o);
                ps += __shfl_xor_sync(0xffffffffu, ps, o);
            }
            if (lane == 0) { qvp[warp] = pv; qskp[warp] = ps; }
        }
        __syncthreads();

        // phase 3: state update S = a_j*S + (bk_j*v_i - a_j*bk_j*Sk_i)
#pragma unroll
        for (int ii = 0; ii < 32; ii++) {
            float g = fmaf(bkj, cur[256 + i0 + ii], -dj * shSk[i0 + ii]);
            S[ii] = fmaf(aj, S[ii], g);
        }
        // fused output: out_j = a_j*u_j + bk_j*(q·v) - a_j*bk_j*(q·Sk); then silu
        if (ig == 0) {
            float qv  = qvp[0] + qvp[1] + qvp[2] + qvp[3];
            float qsk = qskp[0] + qskp[1] + qskp[2] + qskp[3];
            float u = u_part[0][jt] + u_part[1][jt] + u_part[2][jt] + u_part[3][jt];
            float o = fmaf(aj, u, fmaf(bkj, qv, -dj * qsk));
            outb[(size_t)t * Dd + jt] = o * sigf(o);
        }
        __syncthreads();
    }

    if (sfin) {
        float* sf = sfin + (size_t)b * Dd * Dd;
#pragma unroll
        for (int ii = 0; ii < 32; ii++) sf[(size_t)(i0 + ii) * Dd + jt] = S[ii];
    }
}

// --------------------- RMSNorm + scale + residual -------------------------
__global__ void __launch_bounds__(128) rms_kernel(const float* __restrict__ rmsw,
                                                  float* __restrict__ out) {
    int n = blockIdx.x;
    int d = threadIdx.x;
    int lane = d & 31, w = d >> 5;
    __shared__ float red[4];
    float v = g_ol[(size_t)n * Dd + d];
    float ss = v * v;
#pragma unroll
    for (int o = 16; o >= 1; o >>= 1) ss += __shfl_xor_sync(0xffffffffu, ss, o);
    if (lane == 0) red[w] = ss;
    __syncthreads();
    float mean = (red[0] + red[1] + red[2] + red[3]) * (1.f / 128.f);
    float s = rsqrtf(mean + 1e-6f);
    out[(size_t)n * Dd + d] = v * s * rmsw[d] + g_res[(size_t)n * Dd + d];
}

// --------------------------------- launch ---------------------------------
extern "C" void kernel_launch(void* const* d_in, const int* in_sizes, int n_in,
                              void* d_out, int out_size) {
    const float* x      = (const float*)d_in[0];
    const float* state  = (const float*)d_in[1];
    const float* W_in   = (const float*)d_in[2];
    const float* W_gate = (const float*)d_in[3];
    const float* W_out  = (const float*)d_in[4];
    const float* W_res  = (const float*)d_in[5];
    const float* qconvw = (const float*)d_in[6];
    const float* qconvb = (const float*)d_in[7];
    const float* kconvw = (const float*)d_in[8];
    const float* kconvb = (const float*)d_in[9];
    const float* rmsw   = (const float*)d_in[10];
    float* out = (float*)d_out;

    float *qkv, *gg, *res, *outs, *ol;
    cudaGetSymbolAddress((void**)&qkv,  g_qkv);
    cudaGetSymbolAddress((void**)&gg,   g_g);
    cudaGetSymbolAddress((void**)&res,  g_res);
    cudaGetSymbolAddress((void**)&outs, g_out);
    cudaGetSymbolAddress((void**)&ol,   g_ol);

    float* sfin = (out_size >= BLD + BDD) ? (out + BLD) : nullptr;

    // qkv = x @ W_in^T  [16384, 512]
    gemm_kernel<false><<<dim3(512 / 64, NROWS / 64), 256>>>(x, Dd, W_in, qkv, 512);
    // residual = x @ W_res^T  [16384, 128]
    gemm_kernel<false><<<dim3(Dd / 64, NROWS / 64), 256>>>(x, Dd, W_res, res, Dd);
    // g = sigmoid(gate @ W_gate^T)  [16384, 256], gate = qkv cols 384..511
    gemm_kernel<true><<<dim3(256 / 64, NROWS / 64), 256>>>(qkv + 384, 512, W_gate, gg, 256);
    // conv + sigmoid + l2norm + pack
    convpack_kernel<<<NROWS, 128>>>(qconvw, qconvb, kconvw, kconvb);
    // sequential scan (one CTA per batch)
    scan_kernel<<<Bsz, 512>>>(state, sfin);
    // out_lin = outs @ W_out^T
    gemm_kernel<false><<<dim3(Dd / 64, NROWS / 64), 256>>>(outs, Dd, W_out, ol, Dd);
    // rmsnorm + residual
    rms_kernel<<<NROWS, 128>>>(rmsw, out);
}

// round 2
// speedup vs baseline: 1.0441x; 1.0441x over previous
#include <cuda_runtime.h>
#include <cuda_bf16.h>
#include <math.h>

#define Bsz 8
#define Lseq 2048
#define Dd 128
#define NROWS (Bsz * Lseq)          // 16384
#define BLD (NROWS * Dd)            // 2097152
#define BDD (Bsz * Dd * Dd)         // 131072

// ---------------- scratch (device globals; no allocation) ----------------
__device__ float g_qkv[NROWS * 512];   // x @ W_in^T
__device__ float g_g  [NROWS * 256];   // sigmoid(gate @ W_gate^T)
__device__ float g_pk [NROWS * 640];   // packed per-(b,t): q,k,v,alpha,beta (128 each)
__device__ float g_res[NROWS * Dd];    // x @ W_res^T
__device__ float g_out[NROWS * Dd];    // scan outputs (silu(q@S))
__device__ float g_ol [NROWS * Dd];    // outs @ W_out^T

__device__ __forceinline__ float sigf(float x) { return 1.f / (1.f + __expf(-x)); }

// ---------------- generic GEMM: C[n,m] = sum_d A[n,d]*W[m,d] --------------
// N = 16384 rows (fixed), K = 128 (fixed), M multiple of 64.
template <bool SIG>
__global__ void __launch_bounds__(256) gemm_kernel(const float* __restrict__ A, int lda,
                                                   const float* __restrict__ W,
                                                   float* __restrict__ C, int ldc) {
    __shared__ float As[64][17];
    __shared__ float Ws[64][17];
    int bx = blockIdx.x;      // col tile
    int by = blockIdx.y;      // row tile
    int tid = threadIdx.x;
    int tx = tid & 15;
    int ty = tid >> 4;
    int lr  = tid >> 2;       // 0..63 load row
    int lk0 = (tid & 3) * 4;  // 0,4,8,12

    float acc[4][4];
#pragma unroll
    for (int m = 0; m < 4; m++)
#pragma unroll
        for (int n = 0; n < 4; n++) acc[m][n] = 0.f;

    const float* Arow = A + (size_t)(by * 64 + lr) * lda;
    const float* Wrow = W + (size_t)(bx * 64 + lr) * 128;

#pragma unroll 1
    for (int kt = 0; kt < 8; kt++) {
        int k0 = kt * 16;
        float4 av = *reinterpret_cast<const float4*>(Arow + k0 + lk0);
        float4 wv = *reinterpret_cast<const float4*>(Wrow + k0 + lk0);
        As[lr][lk0 + 0] = av.x; As[lr][lk0 + 1] = av.y;
        As[lr][lk0 + 2] = av.z; As[lr][lk0 + 3] = av.w;
        Ws[lr][lk0 + 0] = wv.x; Ws[lr][lk0 + 1] = wv.y;
        Ws[lr][lk0 + 2] = wv.z; Ws[lr][lk0 + 3] = wv.w;
        __syncthreads();
#pragma unroll
        for (int kk = 0; kk < 16; kk++) {
            float a[4], w[4];
#pragma unroll
            for (int m = 0; m < 4; m++) a[m] = As[ty + 16 * m][kk];
#pragma unroll
            for (int n = 0; n < 4; n++) w[n] = Ws[tx + 16 * n][kk];
#pragma unroll
            for (int m = 0; m < 4; m++)
#pragma unroll
                for (int n = 0; n < 4; n++) acc[m][n] = fmaf(a[m], w[n], acc[m][n]);
        }
        __syncthreads();
    }
#pragma unroll
    for (int m = 0; m < 4; m++) {
        int row = by * 64 + ty + 16 * m;
#pragma unroll
        for (int n = 0; n < 4; n++) {
            int col = bx * 64 + tx + 16 * n;
            float v = acc[m][n];
            if (SIG) v = sigf(v);
            C[(size_t)row * ldc + col] = v;
        }
    }
}

// ------------- depthwise conv(K=3) + sigmoid + L2 norm + pack -------------
__global__ void __launch_bounds__(128) convpack_kernel(const float* __restrict__ qw,
                                                       const float* __restrict__ qb,
                                                       const float* __restrict__ kw,
                                                       const float* __restrict__ kb) {
    int n = blockIdx.x;           // b*L + l
    int l = n & (Lseq - 1);
    int d = threadIdx.x;
    int lane = d & 31, w = d >> 5;
    __shared__ float redq[4], redk[4];

    const float* row = g_qkv + (size_t)n * 512;
    // q channel (cols 0..127)
    float qm = (l > 0)        ? row[-512 + d] : 0.f;
    float qc = row[d];
    float qp = (l < Lseq - 1) ? row[512 + d] : 0.f;
    float yq = fmaf(qw[d * 3 + 0], qm, fmaf(qw[d * 3 + 1], qc, fmaf(qw[d * 3 + 2], qp, qb[d])));
    float sq = sigf(yq);
    // k channel (cols 128..255)
    float km = (l > 0)        ? row[-512 + 128 + d] : 0.f;
    float kc = row[128 + d];
    float kp = (l < Lseq - 1) ? row[512 + 128 + d] : 0.f;
    float yk = fmaf(kw[d * 3 + 0], km, fmaf(kw[d * 3 + 1], kc, fmaf(kw[d * 3 + 2], kp, kb[d])));
    float sk = sigf(yk);

    float ssq = sq * sq, ssk = sk * sk;
#pragma unroll
    for (int o = 16; o >= 1; o >>= 1) {
        ssq += __shfl_xor_sync(0xffffffffu, ssq, o);
        ssk += __shfl_xor_sync(0xffffffffu, ssk, o);
    }
    if (lane == 0) { redq[w] = ssq; redk[w] = ssk; }
    __syncthreads();
    float nq = sqrtf(redq[0] + redq[1] + redq[2] + redq[3]);
    float nk = sqrtf(redk[0] + redk[1] + redk[2] + redk[3]);
    float qn = sq / fmaxf(nq, 1e-12f);
    float kn = sk / fmaxf(nk, 1e-12f);

    float* out = g_pk + (size_t)n * 640;
    out[d]       = qn;
    out[128 + d] = kn;
    out[256 + d] = row[256 + d];                       // v
    out[384 + d] = g_g[(size_t)n * 256 + d];           // alpha
    out[512 + d] = g_g[(size_t)n * 256 + 128 + d];     // beta
}

// ------------------------- sequential delta-rule scan ---------------------
// One CTA per batch. 512 threads: tid = ig*128 + jt. Thread owns S[i0..i0+32, jt].
__global__ void __launch_bounds__(512, 1) scan_kernel(const float* __restrict__ state,
                                                      float* __restrict__ sfin) {
    int b = blockIdx.x;
    int tid = threadIdx.x;
    int jt = tid & 127;
    int ig = tid >> 7;            // 0..3
    int lane = tid & 31;
    int warp = tid >> 5;          // 0..15
    int jtg = (tid >> 5) & 3;     // which 32-column group within the 128 columns
    int i0 = ig * 32;

    __shared__ float buf[2][640];
    __shared__ float u_part[4][128];
    __shared__ float sk_part[4][128];
    __shared__ float shSk[128];
    __shared__ float qvp[4], qskp[4];

    float S[32];
    const float* st = state + (size_t)b * Dd * Dd;
#pragma unroll
    for (int ii = 0; ii < 32; ii++) S[ii] = st[(size_t)(i0 + ii) * Dd + jt];

    const float* pkb = g_pk + (size_t)b * Lseq * 640;
    for (int idx = tid; idx < 640; idx += 512) buf[0][idx] = pkb[idx];
    __syncthreads();

    float* outb = g_out + (size_t)b * Lseq * Dd;

    for (int t = 0; t < Lseq; t++) {
        const float* cur = buf[t & 1];
        float kj  = cur[128 + jt];
        float aj  = cur[384 + jt];
        float bj  = cur[512 + jt];
        float bkj = bj * kj;
        float dj  = aj * bkj;

        // prefetch next step (distinct smem buffer)
        if (t + 1 < Lseq) {
            const float* nxt = pkb + (size_t)(t + 1) * 640;
            float* nb = buf[(t + 1) & 1];
            for (int idx = tid; idx < 640; idx += 512) nb[idx] = nxt[idx];
        }

        // phase 1: u partial (over my rows), Sk contributions
        float upart = 0.f;
        float a[32];
#pragma unroll
        for (int ii = 0; ii < 32; ii++) {
            float s = S[ii];
            upart = fmaf(cur[i0 + ii], s, upart);   // q · S_old column partial
            a[ii] = s * kj;
        }
        // warp transpose-reduce: after this, a[0] at lane l = sum over warp's 32 jt
        // of S[i0+l, jt]*k[jt]
#pragma unroll
        for (int o = 16; o >= 1; o >>= 1) {
            bool up = (lane & o) != 0;
#pragma unroll
            for (int m = 0; m < o; m++) {
                float keep = up ? a[m + o] : a[m];
                float give = up ? a[m] : a[m + o];
                float recv = __shfl_xor_sync(0xffffffffu, give, o);
                a[m] = keep + recv;
            }
        }
        u_part[ig][jt] = upart;
        sk_part[jtg][i0 + lane] = a[0];
        __syncthreads();

        // phase 2: combine Sk, scalar reductions q·v and q·Sk
        if (tid < 128) {
            int i = tid;
            float sk = sk_part[0][i] + sk_part[1][i] + sk_part[2][i] + sk_part[3][i];
            shSk[i] = sk;
            float qi = cur[i];
            float pv = qi * cur[256 + i];
            float ps = qi * sk;
#pragma unroll
            for (int o = 16; o >= 1; o >>= 1) {
                pv += __shfl_xor_sync(0xffffffffu, pv, o);
                ps += __shfl_xor_sync(0xffffffffu, ps, o);
            }
            if (lane == 0) { qvp[warp] = pv; qskp[warp] = ps; }
        }
        __syncthreads();

        // phase 3: state update S = a_j*S + (bk_j*v_i - a_j*bk_j*Sk_i)
#pragma unroll
        for (int ii = 0; ii < 32; ii++) {
            float g = fmaf(bkj, cur[256 + i0 + ii], -dj * shSk[i0 + ii]);
            S[ii] = fmaf(aj, S[ii], g);
        }
        // fused output: out_j = a_j*u_j + bk_j*(q·v) - a_j*bk_j*(q·Sk); then silu
        if (ig == 0) {
            float qv  = qvp[0] + qvp[1] + qvp[2] + qvp[3];
            float qsk = qskp[0] + qskp[1] + qskp[2] + qskp[3];
            float u = u_part[0][jt] + u_part[1][jt] + u_part[2][jt] + u_part[3][jt];
            float o = fmaf(aj, u, fmaf(bkj, qv, -dj * qsk));
            outb[(size_t)t * Dd + jt] = o * sigf(o);
        }
        __syncthreads();
    }

    if (sfin) {
        float* sf = sfin + (size_t)b * Dd * Dd;
#pragma unroll
        for (int ii = 0; ii < 32; ii++) sf[(size_t)(i0 + ii) * Dd + jt] = S[ii];
    }
}

// --------------------- RMSNorm + scale + residual -------------------------
__global__ void __launch_bounds__(128) rms_kernel(const float* __restrict__ rmsw,
                                                  float* __restrict__ out) {
    int n = blockIdx.x;
    int d = threadIdx.x;
    int lane = d & 31, w = d >> 5;
    __shared__ float red[4];
    float v = g_ol[(size_t)n * Dd + d];
    float ss = v * v;
#pragma unroll
    for (int o = 16; o >= 1; o >>= 1) ss += __shfl_xor_sync(0xffffffffu, ss, o);
    if (lane == 0) red[w] = ss;
    __syncthreads();
    float mean = (red[0] + red[1] + red[2] + red[3]) * (1.f / 128.f);
    float s = rsqrtf(mean + 1e-6f);
    out[(size_t)n * Dd + d] = v * s * rmsw[d] + g_res[(size_t)n * Dd + d];
}

// --------------------------------- launch ---------------------------------
extern "C" void kernel_launch(void* const* d_in, const int* in_sizes, int n_in,
                              void* d_out, int out_size) {
    const float* x      = (const float*)d_in[0];
    const float* state  = (const float*)d_in[1];
    const float* W_in   = (const float*)d_in[2];
    const float* W_gate = (const float*)d_in[3];
    const float* W_out  = (const float*)d_in[4];
    const float* W_res  = (const float*)d_in[5];
    const float* qconvw = (const float*)d_in[6];
    const float* qconvb = (const float*)d_in[7];
    const float* kconvw = (const float*)d_in[8];
    const float* kconvb = (const float*)d_in[9];
    const float* rmsw   = (const float*)d_in[10];
    float* out = (float*)d_out;

    float *qkv, *gg, *res, *outs, *ol;
    cudaGetSymbolAddress((void**)&qkv,  g_qkv);
    cudaGetSymbolAddress((void**)&gg,   g_g);
    cudaGetSymbolAddress((void**)&res,  g_res);
    cudaGetSymbolAddress((void**)&outs, g_out);
    cudaGetSymbolAddress((void**)&ol,   g_ol);

    float* sfin = (out_size >= BLD + BDD) ? (out + BLD) : nullptr;

    // qkv = x @ W_in^T  [16384, 512]
    gemm_kernel<false><<<dim3(512 / 64, NROWS / 64), 256>>>(x, Dd, W_in, qkv, 512);
    // residual = x @ W_res^T  [16384, 128]
    gemm_kernel<false><<<dim3(Dd / 64, NROWS / 64), 256>>>(x, Dd, W_res, res, Dd);
    // g = sigmoid(gate @ W_gate^T)  [16384, 256], gate = qkv cols 384..511
    gemm_kernel<true><<<dim3(256 / 64, NROWS / 64), 256>>>(qkv + 384, 512, W_gate, gg, 256);
    // conv + sigmoid + l2norm + pack
    convpack_kernel<<<NROWS, 128>>>(qconvw, qconvb, kconvw, kconvb);
    // sequential scan (one CTA per batch)
    scan_kernel<<<Bsz, 512>>>(state, sfin);
    // out_lin = outs @ W_out^T
    gemm_kernel<false><<<dim3(Dd / 64, NROWS / 64), 256>>>(outs, Dd, W_out, ol, Dd);
    // rmsnorm + residual
    rms_kernel<<<NROWS, 128>>>(rmsw, out);
}

// round 3
// speedup vs baseline: 1.0916x; 1.0456x over previous
#include <cuda_runtime.h>
#include <cuda_bf16.h>
#include <math.h>

#define Bsz 8
#define Lseq 2048
#define Dd 128
#define NROWS (Bsz * Lseq)          // 16384
#define BLD (NROWS * Dd)            // 2097152
#define BDD (Bsz * Dd * Dd)         // 131072
#define NG 16                       // row groups per batch (8 rows each)

// ---------------- scratch (device globals; no allocation) ----------------
__device__ float g_qkv[NROWS * 512];
__device__ float g_g  [NROWS * 256];
__device__ float g_pk [NROWS * 640];      // q,k,v,alpha,beta per (b,t)
__device__ float g_res[NROWS * Dd];
__device__ float g_out[NROWS * Dd];
__device__ float g_ol [NROWS * Dd];
__device__ float g_part[NROWS * NG * Dd]; // per (b,t,g): partial q.S over 8 rows

__device__ __forceinline__ float sigf(float x) { return 1.f / (1.f + __expf(-x)); }

// ---------------- generic GEMM: C[n,m] = sum_d A[n,d]*W[m,d] --------------
template <bool SIG>
__global__ void __launch_bounds__(256) gemm_kernel(const float* __restrict__ A, int lda,
                                                   const float* __restrict__ W,
                                                   float* __restrict__ C, int ldc) {
    __shared__ float As[64][17];
    __shared__ float Ws[64][17];
    int bx = blockIdx.x;
    int by = blockIdx.y;
    int tid = threadIdx.x;
    int tx = tid & 15;
    int ty = tid >> 4;
    int lr  = tid >> 2;
    int lk0 = (tid & 3) * 4;

    float acc[4][4];
#pragma unroll
    for (int m = 0; m < 4; m++)
#pragma unroll
        for (int n = 0; n < 4; n++) acc[m][n] = 0.f;

    const float* Arow = A + (size_t)(by * 64 + lr) * lda;
    const float* Wrow = W + (size_t)(bx * 64 + lr) * 128;

#pragma unroll 1
    for (int kt = 0; kt < 8; kt++) {
        int k0 = kt * 16;
        float4 av = *reinterpret_cast<const float4*>(Arow + k0 + lk0);
        float4 wv = *reinterpret_cast<const float4*>(Wrow + k0 + lk0);
        As[lr][lk0 + 0] = av.x; As[lr][lk0 + 1] = av.y;
        As[lr][lk0 + 2] = av.z; As[lr][lk0 + 3] = av.w;
        Ws[lr][lk0 + 0] = wv.x; Ws[lr][lk0 + 1] = wv.y;
        Ws[lr][lk0 + 2] = wv.z; Ws[lr][lk0 + 3] = wv.w;
        __syncthreads();
#pragma unroll
        for (int kk = 0; kk < 16; kk++) {
            float a[4], w[4];
#pragma unroll
            for (int m = 0; m < 4; m++) a[m] = As[ty + 16 * m][kk];
#pragma unroll
            for (int n = 0; n < 4; n++) w[n] = Ws[tx + 16 * n][kk];
#pragma unroll
            for (int m = 0; m < 4; m++)
#pragma unroll
                for (int n = 0; n < 4; n++) acc[m][n] = fmaf(a[m], w[n], acc[m][n]);
        }
        __syncthreads();
    }
#pragma unroll
    for (int m = 0; m < 4; m++) {
        int row = by * 64 + ty + 16 * m;
#pragma unroll
        for (int n = 0; n < 4; n++) {
            int col = bx * 64 + tx + 16 * n;
            float v = acc[m][n];
            if (SIG) v = sigf(v);
            C[(size_t)row * ldc + col] = v;
        }
    }
}

// ------------- depthwise conv(K=3) + sigmoid + L2 norm + pack -------------
__global__ void __launch_bounds__(128) convpack_kernel(const float* __restrict__ qw,
                                                       const float* __restrict__ qb,
                                                       const float* __restrict__ kw,
                                                       const float* __restrict__ kb) {
    int n = blockIdx.x;
    int l = n & (Lseq - 1);
    int d = threadIdx.x;
    int lane = d & 31, w = d >> 5;
    __shared__ float redq[4], redk[4];

    const float* row = g_qkv + (size_t)n * 512;
    float qm = (l > 0)        ? row[-512 + d] : 0.f;
    float qc = row[d];
    float qp = (l < Lseq - 1) ? row[512 + d] : 0.f;
    float yq = fmaf(qw[d * 3 + 0], qm, fmaf(qw[d * 3 + 1], qc, fmaf(qw[d * 3 + 2], qp, qb[d])));
    float sq = sigf(yq);
    float km = (l > 0)        ? row[-512 + 128 + d] : 0.f;
    float kc = row[128 + d];
    float kp = (l < Lseq - 1) ? row[512 + 128 + d] : 0.f;
    float yk = fmaf(kw[d * 3 + 0], km, fmaf(kw[d * 3 + 1], kc, fmaf(kw[d * 3 + 2], kp, kb[d])));
    float sk = sigf(yk);

    float ssq = sq * sq, ssk = sk * sk;
#pragma unroll
    for (int o = 16; o >= 1; o >>= 1) {
        ssq += __shfl_xor_sync(0xffffffffu, ssq, o);
        ssk += __shfl_xor_sync(0xffffffffu, ssk, o);
    }
    if (lane == 0) { redq[w] = ssq; redk[w] = ssk; }
    __syncthreads();
    float nq = sqrtf(redq[0] + redq[1] + redq[2] + redq[3]);
    float nk = sqrtf(redk[0] + redk[1] + redk[2] + redk[3]);
    float qn = sq / fmaxf(nq, 1e-12f);
    float kn = sk / fmaxf(nk, 1e-12f);

    float* out = g_pk + (size_t)n * 640;
    out[d]       = qn;
    out[128 + d] = kn;
    out[256 + d] = row[256 + d];
    out[384 + d] = g_g[(size_t)n * 256 + d];
    out[512 + d] = g_g[(size_t)n * 256 + 128 + d];
}

// ----------------- row-parallel delta-rule scan ---------------------------
// grid = Bsz*NG = 128 CTAs, 256 threads. CTA (b,g) owns rows [g*8, g*8+8).
// Warp w handles row i = g*8 + w; lane owns 4 columns j = lane*4..lane*4+3.
__global__ void __launch_bounds__(256, 1) scan_kernel(const float* __restrict__ state,
                                                      float* __restrict__ sfin) {
    int b = blockIdx.x >> 4;
    int g = blockIdx.x & 15;
    int tid = threadIdx.x;
    int w = tid >> 5;
    int lane = tid & 31;
    int i = g * 8 + w;           // global row within state
    int j0 = lane * 4;

    __shared__ float buf[2][640];
    __shared__ float acc[2][8][132];   // padded to kill bank conflicts on reduce

    // load state row slice
    float4 s = *reinterpret_cast<const float4*>(state + ((size_t)b * Dd + i) * Dd + j0);

    const float* pkb = g_pk + (size_t)b * Lseq * 640;
    for (int idx = tid; idx < 640; idx += 256) buf[0][idx] = pkb[idx];
    __syncthreads();

    float* partb = g_part + ((size_t)b * Lseq * NG + g) * Dd;

#pragma unroll 1
    for (int t = 0; t < Lseq; t++) {
        const float* cur = buf[t & 1];
        int p = t & 1;

        // prefetch next step's vectors
        if (t + 1 < Lseq) {
            const float* nxt = pkb + (size_t)(t + 1) * 640;
            float* nb = buf[(t + 1) & 1];
            for (int idx = tid; idx < 640; idx += 256) nb[idx] = nxt[idx];
        }

        float4 kv = *reinterpret_cast<const float4*>(cur + 128 + j0);
        float4 av = *reinterpret_cast<const float4*>(cur + 384 + j0);
        float4 bv = *reinterpret_cast<const float4*>(cur + 512 + j0);
        float qi = cur[i];
        float vi = cur[256 + i];

        // Sk_i = S[i,:] . k   (warp-local reduce)
        float pr = s.x * kv.x;
        pr = fmaf(s.y, kv.y, pr);
        pr = fmaf(s.z, kv.z, pr);
        pr = fmaf(s.w, kv.w, pr);
#pragma unroll
        for (int o = 16; o >= 1; o >>= 1) pr += __shfl_xor_sync(0xffffffffu, pr, o);
        float Sk = pr;

        // S = a*S - (a*bk)*Sk + v_i*bk
        float bk0 = bv.x * kv.x, bk1 = bv.y * kv.y, bk2 = bv.z * kv.z, bk3 = bv.w * kv.w;
        s.x = fmaf(av.x, s.x, fmaf(vi, bk0, -av.x * bk0 * Sk));
        s.y = fmaf(av.y, s.y, fmaf(vi, bk1, -av.y * bk1 * Sk));
        s.z = fmaf(av.z, s.z, fmaf(vi, bk2, -av.z * bk2 * Sk));
        s.w = fmaf(av.w, s.w, fmaf(vi, bk3, -av.w * bk3 * Sk));

        // per-row output contribution q_i * S_new[i,j]
        float* ac = &acc[p][w][j0];
        ac[0] = qi * s.x; ac[1] = qi * s.y; ac[2] = qi * s.z; ac[3] = qi * s.w;

        __syncthreads();

        // threads 0..127: reduce this CTA's 8 rows, write partial
        if (tid < 128) {
            float r = acc[p][0][tid] + acc[p][1][tid] + acc[p][2][tid] + acc[p][3][tid]
                    + acc[p][4][tid] + acc[p][5][tid] + acc[p][6][tid] + acc[p][7][tid];
            partb[(size_t)t * NG * Dd + tid] = r;
        }
    }

    if (sfin)
        *reinterpret_cast<float4*>(sfin + ((size_t)b * Dd + i) * Dd + j0) = s;
}

// ------------- reduce partials across row-groups + silu -------------------
__global__ void __launch_bounds__(128) reduce_silu_kernel() {
    int n = blockIdx.x;        // b*L + t
    int j = threadIdx.x;
    const float* base = g_part + (size_t)n * NG * Dd + j;
    float r = 0.f;
#pragma unroll
    for (int g = 0; g < NG; g++) r += base[g * Dd];
    g_out[(size_t)n * Dd + j] = r * sigf(r);
}

// --------------------- RMSNorm + scale + residual -------------------------
__global__ void __launch_bounds__(128) rms_kernel(const float* __restrict__ rmsw,
                                                  float* __restrict__ out) {
    int n = blockIdx.x;
    int d = threadIdx.x;
    int lane = d & 31, w = d >> 5;
    __shared__ float red[4];
    float v = g_ol[(size_t)n * Dd + d];
    float ss = v * v;
#pragma unroll
    for (int o = 16; o >= 1; o >>= 1) ss += __shfl_xor_sync(0xffffffffu, ss, o);
    if (lane == 0) red[w] = ss;
    __syncthreads();
    float mean = (red[0] + red[1] + red[2] + red[3]) * (1.f / 128.f);
    float s = rsqrtf(mean + 1e-6f);
    out[(size_t)n * Dd + d] = v * s * rmsw[d] + g_res[(size_t)n * Dd + d];
}

// --------------------------------- launch ---------------------------------
extern "C" void kernel_launch(void* const* d_in, const int* in_sizes, int n_in,
                              void* d_out, int out_size) {
    const float* x      = (const float*)d_in[0];
    const float* state  = (const float*)d_in[1];
    const float* W_in   = (const float*)d_in[2];
    const float* W_gate = (const float*)d_in[3];
    const float* W_out  = (const float*)d_in[4];
    const float* W_res  = (const float*)d_in[5];
    const float* qconvw = (const float*)d_in[6];
    const float* qconvb = (const float*)d_in[7];
    const float* kconvw = (const float*)d_in[8];
    const float* kconvb = (const float*)d_in[9];
    const float* rmsw   = (const float*)d_in[10];
    float* out = (float*)d_out;

    float *qkv, *gg, *res, *outs, *ol;
    cudaGetSymbolAddress((void**)&qkv,  g_qkv);
    cudaGetSymbolAddress((void**)&gg,   g_g);
    cudaGetSymbolAddress((void**)&res,  g_res);
    cudaGetSymbolAddress((void**)&outs, g_out);
    cudaGetSymbolAddress((void**)&ol,   g_ol);

    float* sfin = (out_size >= BLD + BDD) ? (out + BLD) : nullptr;

    // qkv = x @ W_in^T  [16384, 512]
    gemm_kernel<false><<<dim3(512 / 64, NROWS / 64), 256>>>(x, Dd, W_in, qkv, 512);
    // residual = x @ W_res^T
    gemm_kernel<false><<<dim3(Dd / 64, NROWS / 64), 256>>>(x, Dd, W_res, res, Dd);
    // g = sigmoid(gate @ W_gate^T)
    gemm_kernel<true><<<dim3(256 / 64, NROWS / 64), 256>>>(qkv + 384, 512, W_gate, gg, 256);
    // conv + sigmoid + l2norm + pack
    convpack_kernel<<<NROWS, 128>>>(qconvw, qconvb, kconvw, kconvb);
    // row-parallel scan (128 CTAs)
    scan_kernel<<<Bsz * NG, 256>>>(state, sfin);
    // cross-CTA partial reduce + silu
    reduce_silu_kernel<<<NROWS, 128>>>();
    // out_lin = outs @ W_out^T
    gemm_kernel<false><<<dim3(Dd / 64, NROWS / 64), 256>>>(outs, Dd, W_out, ol, Dd);
    // rmsnorm + residual
    rms_kernel<<<NROWS, 128>>>(rmsw, out);
}

// round 4
// speedup vs baseline: 2.4897x; 2.2807x over previous
#include <cuda_runtime.h>
#include <cuda_bf16.h>
#include <math.h>

#define Bsz 8
#define Lseq 2048
#define Dd 128
#define NROWS (Bsz * Lseq)          // 16384
#define BLD (NROWS * Dd)            // 2097152
#define BDD (Bsz * Dd * Dd)         // 131072
#define NG 16                       // row groups per batch (8 rows each)

// ---------------- scratch (device globals; no allocation) ----------------
__device__ float g_qkv[NROWS * 512];
__device__ float g_g  [NROWS * 256];
__device__ float g_pk [NROWS * 640];      // q,k,v,alpha,beta per (b,t)
__device__ float g_res[NROWS * Dd];
__device__ float g_out[NROWS * Dd];
__device__ float g_ol [NROWS * Dd];
__device__ float g_part[NROWS * NG * Dd]; // per (b,t,g): partial q.S over 8 rows

__device__ __forceinline__ float sigf(float x) { return 1.f / (1.f + __expf(-x)); }

// ---------------- generic GEMM: C[n,m] = sum_d A[n,d]*W[m,d] --------------
template <bool SIG>
__global__ void __launch_bounds__(256) gemm_kernel(const float* __restrict__ A, int lda,
                                                   const float* __restrict__ W,
                                                   float* __restrict__ C, int ldc) {
    __shared__ float As[64][17];
    __shared__ float Ws[64][17];
    int bx = blockIdx.x;
    int by = blockIdx.y;
    int tid = threadIdx.x;
    int tx = tid & 15;
    int ty = tid >> 4;
    int lr  = tid >> 2;
    int lk0 = (tid & 3) * 4;

    float acc[4][4];
#pragma unroll
    for (int m = 0; m < 4; m++)
#pragma unroll
        for (int n = 0; n < 4; n++) acc[m][n] = 0.f;

    const float* Arow = A + (size_t)(by * 64 + lr) * lda;
    const float* Wrow = W + (size_t)(bx * 64 + lr) * 128;

#pragma unroll 1
    for (int kt = 0; kt < 8; kt++) {
        int k0 = kt * 16;
        float4 av = *reinterpret_cast<const float4*>(Arow + k0 + lk0);
        float4 wv = *reinterpret_cast<const float4*>(Wrow + k0 + lk0);
        As[lr][lk0 + 0] = av.x; As[lr][lk0 + 1] = av.y;
        As[lr][lk0 + 2] = av.z; As[lr][lk0 + 3] = av.w;
        Ws[lr][lk0 + 0] = wv.x; Ws[lr][lk0 + 1] = wv.y;
        Ws[lr][lk0 + 2] = wv.z; Ws[lr][lk0 + 3] = wv.w;
        __syncthreads();
#pragma unroll
        for (int kk = 0; kk < 16; kk++) {
            float a[4], w[4];
#pragma unroll
            for (int m = 0; m < 4; m++) a[m] = As[ty + 16 * m][kk];
#pragma unroll
            for (int n = 0; n < 4; n++) w[n] = Ws[tx + 16 * n][kk];
#pragma unroll
            for (int m = 0; m < 4; m++)
#pragma unroll
                for (int n = 0; n < 4; n++) acc[m][n] = fmaf(a[m], w[n], acc[m][n]);
        }
        __syncthreads();
    }
#pragma unroll
    for (int m = 0; m < 4; m++) {
        int row = by * 64 + ty + 16 * m;
#pragma unroll
        for (int n = 0; n < 4; n++) {
            int col = bx * 64 + tx + 16 * n;
            float v = acc[m][n];
            if (SIG) v = sigf(v);
            C[(size_t)row * ldc + col] = v;
        }
    }
}

// ------------- depthwise conv(K=3) + sigmoid + L2 norm + pack -------------
__global__ void __launch_bounds__(128) convpack_kernel(const float* __restrict__ qw,
                                                       const float* __restrict__ qb,
                                                       const float* __restrict__ kw,
                                                       const float* __restrict__ kb) {
    int n = blockIdx.x;
    int l = n & (Lseq - 1);
    int d = threadIdx.x;
    int lane = d & 31, w = d >> 5;
    __shared__ float redq[4], redk[4];

    const float* row = g_qkv + (size_t)n * 512;
    float qm = (l > 0)        ? row[-512 + d] : 0.f;
    float qc = row[d];
    float qp = (l < Lseq - 1) ? row[512 + d] : 0.f;
    float yq = fmaf(qw[d * 3 + 0], qm, fmaf(qw[d * 3 + 1], qc, fmaf(qw[d * 3 + 2], qp, qb[d])));
    float sq = sigf(yq);
    float km = (l > 0)        ? row[-512 + 128 + d] : 0.f;
    float kc = row[128 + d];
    float kp = (l < Lseq - 1) ? row[512 + 128 + d] : 0.f;
    float yk = fmaf(kw[d * 3 + 0], km, fmaf(kw[d * 3 + 1], kc, fmaf(kw[d * 3 + 2], kp, kb[d])));
    float sk = sigf(yk);

    float ssq = sq * sq, ssk = sk * sk;
#pragma unroll
    for (int o = 16; o >= 1; o >>= 1) {
        ssq += __shfl_xor_sync(0xffffffffu, ssq, o);
        ssk += __shfl_xor_sync(0xffffffffu, ssk, o);
    }
    if (lane == 0) { redq[w] = ssq; redk[w] = ssk; }
    __syncthreads();
    float nq = sqrtf(redq[0] + redq[1] + redq[2] + redq[3]);
    float nk = sqrtf(redk[0] + redk[1] + redk[2] + redk[3]);
    float qn = sq / fmaxf(nq, 1e-12f);
    float kn = sk / fmaxf(nk, 1e-12f);

    float* out = g_pk + (size_t)n * 640;
    out[d]       = qn;
    out[128 + d] = kn;
    out[256 + d] = row[256 + d];
    out[384 + d] = g_g[(size_t)n * 256 + d];
    out[512 + d] = g_g[(size_t)n * 256 + 128 + d];
}

// ----------------- row-parallel delta-rule scan ---------------------------
// grid = Bsz*NG = 128 CTAs, 256 threads. CTA (b,g) owns rows [g*8, g*8+8).
// Warp w handles row i = g*8 + w; lane owns 4 columns j = lane*4..lane*4+3.
// Step vectors are loaded straight from global one step AHEAD into registers,
// so LDG latency overlaps the shfl-reduce/update/barrier of the current step.
__global__ void __launch_bounds__(256, 1) scan_kernel(const float* __restrict__ state,
                                                      float* __restrict__ sfin) {
    int b = blockIdx.x >> 4;
    int g = blockIdx.x & 15;
    int tid = threadIdx.x;
    int w = tid >> 5;
    int lane = tid & 31;
    int i = g * 8 + w;           // row this warp owns
    int j0 = lane * 4;

    __shared__ float acc[2][8][132];   // padded: bank-conflict-free reduce

    float4 s = *reinterpret_cast<const float4*>(state + ((size_t)b * Dd + i) * Dd + j0);

    const float* pkb = g_pk + (size_t)b * Lseq * 640;
    float* partb = g_part + ((size_t)b * Lseq * NG + g) * Dd;

    // prime step 0 into registers
    float4 kv = *reinterpret_cast<const float4*>(pkb + 128 + j0);
    float4 av = *reinterpret_cast<const float4*>(pkb + 384 + j0);
    float4 bv = *reinterpret_cast<const float4*>(pkb + 512 + j0);
    float qi = pkb[i];
    float vi = pkb[256 + i];

#pragma unroll 1
    for (int t = 0; t < Lseq; t++) {
        int p = t & 1;

        // issue next step's loads NOW (no consumer until loop bottom)
        float4 nk, na, nb;
        float nq = 0.f, nv = 0.f;
        nk.x = nk.y = nk.z = nk.w = 0.f;
        na = nk; nb = nk;
        if (t + 1 < Lseq) {
            const float* pn = pkb + (size_t)(t + 1) * 640;
            nk = *reinterpret_cast<const float4*>(pn + 128 + j0);
            na = *reinterpret_cast<const float4*>(pn + 384 + j0);
            nb = *reinterpret_cast<const float4*>(pn + 512 + j0);
            nq = pn[i];
            nv = pn[256 + i];
        }

        // Sk_i = S[i,:] . k   (warp-local butterfly)
        float pr = s.x * kv.x;
        pr = fmaf(s.y, kv.y, pr);
        pr = fmaf(s.z, kv.z, pr);
        pr = fmaf(s.w, kv.w, pr);
#pragma unroll
        for (int o = 16; o >= 1; o >>= 1) pr += __shfl_xor_sync(0xffffffffu, pr, o);
        float Sk = pr;

        // S = a*S + (v_i*bk - a*bk*Sk)
        float bk0 = bv.x * kv.x, bk1 = bv.y * kv.y, bk2 = bv.z * kv.z, bk3 = bv.w * kv.w;
        s.x = fmaf(av.x, s.x, fmaf(vi, bk0, -av.x * bk0 * Sk));
        s.y = fmaf(av.y, s.y, fmaf(vi, bk1, -av.y * bk1 * Sk));
        s.z = fmaf(av.z, s.z, fmaf(vi, bk2, -av.z * bk2 * Sk));
        s.w = fmaf(av.w, s.w, fmaf(vi, bk3, -av.w * bk3 * Sk));

        // per-row output contribution q_i * S_new[i,:]
        float* ac = &acc[p][w][j0];
        ac[0] = qi * s.x; ac[1] = qi * s.y; ac[2] = qi * s.z; ac[3] = qi * s.w;

        __syncthreads();

        // 128 threads reduce the 8 rows, write the CTA partial
        if (tid < 128) {
            float r = acc[p][0][tid] + acc[p][1][tid] + acc[p][2][tid] + acc[p][3][tid]
                    + acc[p][4][tid] + acc[p][5][tid] + acc[p][6][tid] + acc[p][7][tid];
            partb[(size_t)t * NG * Dd + tid] = r;
        }

        // rotate prefetched registers in
        kv = nk; av = na; bv = nb; qi = nq; vi = nv;
    }

    if (sfin)
        *reinterpret_cast<float4*>(sfin + ((size_t)b * Dd + i) * Dd + j0) = s;
}

// ------------- reduce partials across row-groups + silu -------------------
__global__ void __launch_bounds__(128) reduce_silu_kernel() {
    int n = blockIdx.x;        // b*L + t
    int j = threadIdx.x;
    const float* base = g_part + (size_t)n * NG * Dd + j;
    float r = 0.f;
#pragma unroll
    for (int g = 0; g < NG; g++) r += base[g * Dd];
    g_out[(size_t)n * Dd + j] = r * sigf(r);
}

// --------------------- RMSNorm + scale + residual -------------------------
__global__ void __launch_bounds__(128) rms_kernel(const float* __restrict__ rmsw,
                                                  float* __restrict__ out) {
    int n = blockIdx.x;
    int d = threadIdx.x;
    int lane = d & 31, w = d >> 5;
    __shared__ float red[4];
    float v = g_ol[(size_t)n * Dd + d];
    float ss = v * v;
#pragma unroll
    for (int o = 16; o >= 1; o >>= 1) ss += __shfl_xor_sync(0xffffffffu, ss, o);
    if (lane == 0) red[w] = ss;
    __syncthreads();
    float mean = (red[0] + red[1] + red[2] + red[3]) * (1.f / 128.f);
    float s = rsqrtf(mean + 1e-6f);
    out[(size_t)n * Dd + d] = v * s * rmsw[d] + g_res[(size_t)n * Dd + d];
}

// --------------------------------- launch ---------------------------------
extern "C" void kernel_launch(void* const* d_in, const int* in_sizes, int n_in,
                              void* d_out, int out_size) {
    const float* x      = (const float*)d_in[0];
    const float* state  = (const float*)d_in[1];
    const float* W_in   = (const float*)d_in[2];
    const float* W_gate = (const float*)d_in[3];
    const float* W_out  = (const float*)d_in[4];
    const float* W_res  = (const float*)d_in[5];
    const float* qconvw = (const float*)d_in[6];
    const float* qconvb = (const float*)d_in[7];
    const float* kconvw = (const float*)d_in[8];
    const float* kconvb = (const float*)d_in[9];
    const float* rmsw   = (const float*)d_in[10];
    float* out = (float*)d_out;

    float *qkv, *gg, *res, *outs, *ol;
    cudaGetSymbolAddress((void**)&qkv,  g_qkv);
    cudaGetSymbolAddress((void**)&gg,   g_g);
    cudaGetSymbolAddress((void**)&res,  g_res);
    cudaGetSymbolAddress((void**)&outs, g_out);
    cudaGetSymbolAddress((void**)&ol,   g_ol);

    float* sfin = (out_size >= BLD + BDD) ? (out + BLD) : nullptr;

    gemm_kernel<false><<<dim3(512 / 64, NROWS / 64), 256>>>(x, Dd, W_in, qkv, 512);
    gemm_kernel<false><<<dim3(Dd / 64, NROWS / 64), 256>>>(x, Dd, W_res, res, Dd);
    gemm_kernel<true><<<dim3(256 / 64, NROWS / 64), 256>>>(qkv + 384, 512, W_gate, gg, 256);
    convpack_kernel<<<NROWS, 128>>>(qconvw, qconvb, kconvw, kconvb);
    scan_kernel<<<Bsz * NG, 256>>>(state, sfin);
    reduce_silu_kernel<<<NROWS, 128>>>();
    gemm_kernel<false><<<dim3(Dd / 64, NROWS / 64), 256>>>(outs, Dd, W_out, ol, Dd);
    rms_kernel<<<NROWS, 128>>>(rmsw, out);
}

// round 5
// speedup vs baseline: 3.8022x; 1.5271x over previous
#include <cuda_runtime.h>
#include <cuda_bf16.h>
#include <math.h>

#define Bsz 8
#define Lseq 2048
#define Dd 128
#define NROWS (Bsz * Lseq)          // 16384
#define BLD (NROWS * Dd)            // 2097152
#define BDD (Bsz * Dd * Dd)         // 131072
#define NG 16                       // row groups per batch (8 rows each)

// ---------------- scratch (device globals; no allocation) ----------------
__device__ float g_qkv[NROWS * 512];
__device__ float g_g  [NROWS * 256];
__device__ float g_pk [NROWS * 640];      // q,k,v,alpha,beta per (b,t)
__device__ float g_res[NROWS * Dd];
__device__ float g_out[NROWS * Dd];
__device__ float g_ol [NROWS * Dd];
__device__ float g_part[NROWS * NG * Dd]; // per (b,t,g): partial q.S over 8 rows

__device__ __forceinline__ float sigf(float x) { return 1.f / (1.f + __expf(-x)); }

// ---------------- generic GEMM: C[n,m] = sum_d A[n,d]*W[m,d] --------------
template <bool SIG>
__global__ void __launch_bounds__(256) gemm_kernel(const float* __restrict__ A, int lda,
                                                   const float* __restrict__ W,
                                                   float* __restrict__ C, int ldc) {
    __shared__ float As[64][17];
    __shared__ float Ws[64][17];
    int bx = blockIdx.x;
    int by = blockIdx.y;
    int tid = threadIdx.x;
    int tx = tid & 15;
    int ty = tid >> 4;
    int lr  = tid >> 2;
    int lk0 = (tid & 3) * 4;

    float acc[4][4];
#pragma unroll
    for (int m = 0; m < 4; m++)
#pragma unroll
        for (int n = 0; n < 4; n++) acc[m][n] = 0.f;

    const float* Arow = A + (size_t)(by * 64 + lr) * lda;
    const float* Wrow = W + (size_t)(bx * 64 + lr) * 128;

#pragma unroll 1
    for (int kt = 0; kt < 8; kt++) {
        int k0 = kt * 16;
        float4 av = *reinterpret_cast<const float4*>(Arow + k0 + lk0);
        float4 wv = *reinterpret_cast<const float4*>(Wrow + k0 + lk0);
        As[lr][lk0 + 0] = av.x; As[lr][lk0 + 1] = av.y;
        As[lr][lk0 + 2] = av.z; As[lr][lk0 + 3] = av.w;
        Ws[lr][lk0 + 0] = wv.x; Ws[lr][lk0 + 1] = wv.y;
        Ws[lr][lk0 + 2] = wv.z; Ws[lr][lk0 + 3] = wv.w;
        __syncthreads();
#pragma unroll
        for (int kk = 0; kk < 16; kk++) {
            float a[4], w[4];
#pragma unroll
            for (int m = 0; m < 4; m++) a[m] = As[ty + 16 * m][kk];
#pragma unroll
            for (int n = 0; n < 4; n++) w[n] = Ws[tx + 16 * n][kk];
#pragma unroll
            for (int m = 0; m < 4; m++)
#pragma unroll
                for (int n = 0; n < 4; n++) acc[m][n] = fmaf(a[m], w[n], acc[m][n]);
        }
        __syncthreads();
    }
#pragma unroll
    for (int m = 0; m < 4; m++) {
        int row = by * 64 + ty + 16 * m;
#pragma unroll
        for (int n = 0; n < 4; n++) {
            int col = bx * 64 + tx + 16 * n;
            float v = acc[m][n];
            if (SIG) v = sigf(v);
            C[(size_t)row * ldc + col] = v;
        }
    }
}

// ------------- depthwise conv(K=3) + sigmoid + L2 norm + pack -------------
__global__ void __launch_bounds__(128) convpack_kernel(const float* __restrict__ qw,
                                                       const float* __restrict__ qb,
                                                       const float* __restrict__ kw,
                                                       const float* __restrict__ kb) {
    int n = blockIdx.x;
    int l = n & (Lseq - 1);
    int d = threadIdx.x;
    int lane = d & 31, w = d >> 5;
    __shared__ float redq[4], redk[4];

    const float* row = g_qkv + (size_t)n * 512;
    float qm = (l > 0)        ? row[-512 + d] : 0.f;
    float qc = row[d];
    float qp = (l < Lseq - 1) ? row[512 + d] : 0.f;
    float yq = fmaf(qw[d * 3 + 0], qm, fmaf(qw[d * 3 + 1], qc, fmaf(qw[d * 3 + 2], qp, qb[d])));
    float sq = sigf(yq);
    float km = (l > 0)        ? row[-512 + 128 + d] : 0.f;
    float kc = row[128 + d];
    float kp = (l < Lseq - 1) ? row[512 + 128 + d] : 0.f;
    float yk = fmaf(kw[d * 3 + 0], km, fmaf(kw[d * 3 + 1], kc, fmaf(kw[d * 3 + 2], kp, kb[d])));
    float sk = sigf(yk);

    float ssq = sq * sq, ssk = sk * sk;
#pragma unroll
    for (int o = 16; o >= 1; o >>= 1) {
        ssq += __shfl_xor_sync(0xffffffffu, ssq, o);
        ssk += __shfl_xor_sync(0xffffffffu, ssk, o);
    }
    if (lane == 0) { redq[w] = ssq; redk[w] = ssk; }
    __syncthreads();
    float nq = sqrtf(redq[0] + redq[1] + redq[2] + redq[3]);
    float nk = sqrtf(redk[0] + redk[1] + redk[2] + redk[3]);
    float qn = sq / fmaxf(nq, 1e-12f);
    float kn = sk / fmaxf(nk, 1e-12f);

    float* out = g_pk + (size_t)n * 640;
    out[d]       = qn;
    out[128 + d] = kn;
    out[256 + d] = row[256 + d];
    out[384 + d] = g_g[(size_t)n * 256 + d];
    out[512 + d] = g_g[(size_t)n * 256 + 128 + d];
}

// ----------------- row-parallel delta-rule scan ---------------------------
// grid = Bsz*NG = 128 CTAs, 256 threads. Warp w owns row i = g*8+w; lane owns
// 4 cols. Step vectors prefetched 2 deep in registers. Output contributions
// buffered 4 steps in smem; ONE barrier + cooperative reduce per 4 steps.
__global__ void __launch_bounds__(256, 1) scan_kernel(const float* __restrict__ state,
                                                      float* __restrict__ sfin) {
    int b = blockIdx.x >> 4;
    int g = blockIdx.x & 15;
    int tid = threadIdx.x;
    int w = tid >> 5;
    int lane = tid & 31;
    int i = g * 8 + w;
    int j0 = lane * 4;

    __shared__ float acc[8][8][132];   // [slot][row][col] padded

    float4 s = *reinterpret_cast<const float4*>(state + ((size_t)b * Dd + i) * Dd + j0);

    const float* pkb = g_pk + (size_t)b * Lseq * 640;
    float* partb = g_part + ((size_t)b * Lseq * NG + g) * Dd;

    // prime steps 0 and 1 into registers
    float4 kv = *reinterpret_cast<const float4*>(pkb + 128 + j0);
    float4 av = *reinterpret_cast<const float4*>(pkb + 384 + j0);
    float4 bv = *reinterpret_cast<const float4*>(pkb + 512 + j0);
    float qi = pkb[i];
    float vi = pkb[256 + i];
    float4 kv1 = *reinterpret_cast<const float4*>(pkb + 640 + 128 + j0);
    float4 av1 = *reinterpret_cast<const float4*>(pkb + 640 + 384 + j0);
    float4 bv1 = *reinterpret_cast<const float4*>(pkb + 640 + 512 + j0);
    float qi1 = pkb[640 + i];
    float vi1 = pkb[640 + 256 + i];

    int rtt  = tid >> 6;          // 0..3 : time slot this thread reduces
    int rcol = tid & 63;          // cols rcol and rcol+64

#pragma unroll 1
    for (int t0 = 0; t0 < Lseq; t0 += 4) {
#pragma unroll
        for (int tt = 0; tt < 4; tt++) {
            int t = t0 + tt;
            int slot = (t0 & 4) | tt;

            // issue loads for t+2 (clamped; unused past the end)
            int tn = t + 2 < Lseq ? t + 2 : Lseq - 1;
            const float* pn = pkb + (size_t)tn * 640;
            float4 nk = *reinterpret_cast<const float4*>(pn + 128 + j0);
            float4 na = *reinterpret_cast<const float4*>(pn + 384 + j0);
            float4 nb = *reinterpret_cast<const float4*>(pn + 512 + j0);
            float nq = pn[i];
            float nv = pn[256 + i];

            // Sk_i = S[i,:] . k
            float pr = s.x * kv.x;
            pr = fmaf(s.y, kv.y, pr);
            pr = fmaf(s.z, kv.z, pr);
            pr = fmaf(s.w, kv.w, pr);
#pragma unroll
            for (int o = 16; o >= 1; o >>= 1) pr += __shfl_xor_sync(0xffffffffu, pr, o);
            float Sk = pr;

            // S = a*S + (v_i*bk - a*bk*Sk)
            float bk0 = bv.x * kv.x, bk1 = bv.y * kv.y;
            float bk2 = bv.z * kv.z, bk3 = bv.w * kv.w;
            s.x = fmaf(av.x, s.x, fmaf(vi, bk0, -av.x * bk0 * Sk));
            s.y = fmaf(av.y, s.y, fmaf(vi, bk1, -av.y * bk1 * Sk));
            s.z = fmaf(av.z, s.z, fmaf(vi, bk2, -av.z * bk2 * Sk));
            s.w = fmaf(av.w, s.w, fmaf(vi, bk3, -av.w * bk3 * Sk));

            float* ac = &acc[slot][w][j0];
            ac[0] = qi * s.x; ac[1] = qi * s.y; ac[2] = qi * s.z; ac[3] = qi * s.w;

            // rotate prefetch pipeline
            kv = kv1; av = av1; bv = bv1; qi = qi1; vi = vi1;
            kv1 = nk; av1 = na; bv1 = nb; qi1 = nq; vi1 = nv;
        }

        __syncthreads();

        // cooperative reduce of the 4 just-written slots (64 threads / slot)
        {
            int slot = (t0 & 4) | rtt;
            float r0 = 0.f, r1 = 0.f;
#pragma unroll
            for (int rr = 0; rr < 8; rr++) {
                r0 += acc[slot][rr][rcol];
                r1 += acc[slot][rr][rcol + 64];
            }
            float* dst = partb + (size_t)(t0 + rtt) * NG * Dd;
            dst[rcol]      = r0;
            dst[rcol + 64] = r1;
        }
        // no second barrier needed: next group writes the other 4 slots,
        // and these slots are rewritten only after the NEXT barrier.
    }

    if (sfin)
        *reinterpret_cast<float4*>(sfin + ((size_t)b * Dd + i) * Dd + j0) = s;
}

// ------------- reduce partials across row-groups + silu -------------------
__global__ void __launch_bounds__(128) reduce_silu_kernel() {
    int n = blockIdx.x;        // b*L + t
    int j = threadIdx.x;
    const float* base = g_part + (size_t)n * NG * Dd + j;
    float r = 0.f;
#pragma unroll
    for (int g = 0; g < NG; g++) r += base[g * Dd];
    g_out[(size_t)n * Dd + j] = r * sigf(r);
}

// --------------------- RMSNorm + scale + residual -------------------------
__global__ void __launch_bounds__(128) rms_kernel(const float* __restrict__ rmsw,
                                                  float* __restrict__ out) {
    int n = blockIdx.x;
    int d = threadIdx.x;
    int lane = d & 31, w = d >> 5;
    __shared__ float red[4];
    float v = g_ol[(size_t)n * Dd + d];
    float ss = v * v;
#pragma unroll
    for (int o = 16; o >= 1; o >>= 1) ss += __shfl_xor_sync(0xffffffffu, ss, o);
    if (lane == 0) red[w] = ss;
    __syncthreads();
    float mean = (red[0] + red[1] + red[2] + red[3]) * (1.f / 128.f);
    float s = rsqrtf(mean + 1e-6f);
    out[(size_t)n * Dd + d] = v * s * rmsw[d] + g_res[(size_t)n * Dd + d];
}

// --------------------------------- launch ---------------------------------
extern "C" void kernel_launch(void* const* d_in, const int* in_sizes, int n_in,
                              void* d_out, int out_size) {
    const float* x      = (const float*)d_in[0];
    const float* state  = (const float*)d_in[1];
    const float* W_in   = (const float*)d_in[2];
    const float* W_gate = (const float*)d_in[3];
    const float* W_out  = (const float*)d_in[4];
    const float* W_res  = (const float*)d_in[5];
    const float* qconvw = (const float*)d_in[6];
    const float* qconvb = (const float*)d_in[7];
    const float* kconvw = (const float*)d_in[8];
    const float* kconvb = (const float*)d_in[9];
    const float* rmsw   = (const float*)d_in[10];
    float* out = (float*)d_out;

    float *qkv, *gg, *res, *outs, *ol;
    cudaGetSymbolAddress((void**)&qkv,  g_qkv);
    cudaGetSymbolAddress((void**)&gg,   g_g);
    cudaGetSymbolAddress((void**)&res,  g_res);
    cudaGetSymbolAddress((void**)&outs, g_out);
    cudaGetSymbolAddress((void**)&ol,   g_ol);

    float* sfin = (out_size >= BLD + BDD) ? (out + BLD) : nullptr;

    gemm_kernel<false><<<dim3(512 / 64, NROWS / 64), 256>>>(x, Dd, W_in, qkv, 512);
    gemm_kernel<false><<<dim3(Dd / 64, NROWS / 64), 256>>>(x, Dd, W_res, res, Dd);
    gemm_kernel<true><<<dim3(256 / 64, NROWS / 64), 256>>>(qkv + 384, 512, W_gate, gg, 256);
    convpack_kernel<<<NROWS, 128>>>(qconvw, qconvb, kconvw, kconvb);
    scan_kernel<<<Bsz * NG, 256>>>(state, sfin);
    reduce_silu_kernel<<<NROWS, 128>>>();
    gemm_kernel<false><<<dim3(Dd / 64, NROWS / 64), 256>>>(outs, Dd, W_out, ol, Dd);
    rms_kernel<<<NROWS, 128>>>(rmsw, out);
}